// round 6
// baseline (speedup 1.0000x reference)
#include <cuda_runtime.h>
#include <cuda_bf16.h>
#include <math.h>

// Scratch (device globals — no allocation allowed)
__device__ float g_h[8 * 2048 * 128];   // h = text @ W
__device__ float g_e1[8 * 2048];
__device__ float g_e2[8 * 2048];
__device__ float g_m2[8];               // per-batch max of e2
__device__ float g_wsum[8 * 2048];      // softmax denominators (block-local use)

#define ALPHA_LR 0.2f
#define LOG2E 1.4426950408889634f

// ---------------------------------------------------------------------------
// f32x2 helpers (Blackwell packed fp32 FMA — only reachable via PTX)
// ---------------------------------------------------------------------------
__device__ __forceinline__ unsigned long long pack_dup(float v) {
    unsigned long long r;
    asm("mov.b64 %0, {%1, %1};" : "=l"(r) : "f"(v));
    return r;
}
__device__ __forceinline__ void fma2(unsigned long long& acc, unsigned long long v,
                                     unsigned long long w) {
    asm("fma.rn.f32x2 %0, %1, %2, %0;" : "+l"(acc) : "l"(v), "l"(w));
}
__device__ __forceinline__ void unpack2(unsigned long long p, float& lo, float& hi) {
    asm("mov.b64 {%0, %1}, %2;" : "=f"(lo), "=f"(hi) : "l"(p));
}
__device__ __forceinline__ float ex2_approx(float x) {
    float r;
    asm("ex2.approx.ftz.f32 %0, %1;" : "=f"(r) : "f"(x));
    return r;
}

// ---------------------------------------------------------------------------
// Kernel 1: h = text @ W    (16384 x 128) = (16384 x 128) @ (128 x 128)
// ---------------------------------------------------------------------------
__global__ __launch_bounds__(256) void gemm_h_kernel(const float* __restrict__ text,
                                                     const float* __restrict__ W) {
    __shared__ float ts[64][33];
    __shared__ float ws[32][128];

    const int tid = threadIdx.x;
    const int il  = tid & 63;
    const int fg  = tid >> 6;
    const size_t row0 = (size_t)blockIdx.x * 64;

    unsigned long long acc[16];
#pragma unroll
    for (int m = 0; m < 16; m++) acc[m] = 0ULL;

    for (int k0 = 0; k0 < 128; k0 += 32) {
        __syncthreads();
#pragma unroll
        for (int q = 0; q < 2; q++) {
            int idx = tid + q * 256;
            int r   = idx >> 3;
            int kk4 = idx & 7;
            float4 v = *(const float4*)(text + (row0 + r) * 128 + k0 + kk4 * 4);
            ts[r][kk4 * 4 + 0] = v.x; ts[r][kk4 * 4 + 1] = v.y;
            ts[r][kk4 * 4 + 2] = v.z; ts[r][kk4 * 4 + 3] = v.w;
        }
#pragma unroll
        for (int q = 0; q < 4; q++) {
            int idx = tid + q * 256;
            int kr  = idx >> 5;
            int c4  = idx & 31;
            *(float4*)(&ws[kr][c4 * 4]) = *(const float4*)(W + (size_t)(k0 + kr) * 128 + c4 * 4);
        }
        __syncthreads();

#pragma unroll
        for (int kk = 0; kk < 32; kk++) {
            unsigned long long a2 = pack_dup(ts[il][kk]);
            const ulonglong2* wr = (const ulonglong2*)(&ws[kk][fg * 32]);
#pragma unroll
            for (int m = 0; m < 8; m++) {
                ulonglong2 v = wr[m];
                fma2(acc[2 * m],     v.x, a2);
                fma2(acc[2 * m + 1], v.y, a2);
            }
        }
    }

    float* hrow = g_h + (row0 + il) * 128 + fg * 32;
#pragma unroll
    for (int m = 0; m < 8; m++) {
        float4 o;
        unpack2(acc[2 * m],     o.x, o.y);
        unpack2(acc[2 * m + 1], o.z, o.w);
        *(float4*)(hrow + m * 4) = o;
    }
}

// ---------------------------------------------------------------------------
// Kernel 2: e1[row] = h[row,:].a1 ; e2[row] = h[row,:].a2   (warp per row)
// ---------------------------------------------------------------------------
__global__ __launch_bounds__(256) void e_kernel(const float* __restrict__ a) {
    const int warp = threadIdx.x >> 5;
    const int lane = threadIdx.x & 31;
    const size_t row = (size_t)blockIdx.x * 8 + warp;

    float4 hv = *(const float4*)(g_h + row * 128 + lane * 4);
    float4 a1 = *(const float4*)(a + lane * 4);
    float4 a2 = *(const float4*)(a + 128 + lane * 4);

    float s1 = hv.x * a1.x + hv.y * a1.y + hv.z * a1.z + hv.w * a1.w;
    float s2 = hv.x * a2.x + hv.y * a2.y + hv.z * a2.z + hv.w * a2.w;
#pragma unroll
    for (int o = 16; o > 0; o >>= 1) {
        s1 += __shfl_xor_sync(0xFFFFFFFFu, s1, o);
        s2 += __shfl_xor_sync(0xFFFFFFFFu, s2, o);
    }
    if (lane == 0) { g_e1[row] = s1; g_e2[row] = s2; }
}

// ---------------------------------------------------------------------------
// Kernel 3: m2[b] = max_j e2[b,j]
// ---------------------------------------------------------------------------
__global__ __launch_bounds__(256) void max_kernel() {
    __shared__ float red[256];
    const int b = blockIdx.x;
    float m = -INFINITY;
    for (int j = threadIdx.x; j < 2048; j += 256) m = fmaxf(m, g_e2[b * 2048 + j]);
    red[threadIdx.x] = m;
    __syncthreads();
    for (int s = 128; s > 0; s >>= 1) {
        if (threadIdx.x < s) red[threadIdx.x] = fmaxf(red[threadIdx.x], red[threadIdx.x + s]);
        __syncthreads();
    }
    if (threadIdx.x == 0) g_m2[b] = red[0];
}

// ---------------------------------------------------------------------------
// Kernel 4: attention, register-tiled.
// Block = 64 i-rows x 128 f, 128 threads. Thread = 4 i x 16 f (64 accums).
// Per j-tile (64): phase A computes w[64j][64i] into smem (each exp ONCE,
// wsum folded in), phase B is a pure-FMA rank-64 update.
//   w_ij = exp2(LR(e1_i+e2_j)*log2e - m_i*log2e),  m_i = LR(e1_i + max_j e2_j)
// ---------------------------------------------------------------------------
__global__ __launch_bounds__(128, 4) void attn_kernel(float* __restrict__ out) {
    __shared__ float hs[64][128];   // 32 KB
    __shared__ float wt[64][64];    // 16 KB (w transposed: wt[j][i])

    const int tid = threadIdx.x;
    const int tf  = tid & 7;        // f-group: f0 = tf*16
    const int ti  = tid >> 3;       // i-group: rows i0 + ti*4 .. +3
    const int iA  = tid & 63;       // phase-A row
    const int jh  = tid >> 6;       // phase-A j-half (0/1)

    const int b = blockIdx.y;
    const size_t base = (size_t)b * 2048;
    const int i0 = blockIdx.x * 64;
    const float* hb = g_h + base * 128;

    // prologue: per-thread phase-A constants
    const float e1A = g_e1[base + i0 + iA];
    const float m2b = g_m2[b];
    const float ms  = e1A + m2b;
    const float mi  = fmaxf(ms, 0.f) + ALPHA_LR * fminf(ms, 0.f);
    const float e1L = e1A * LOG2E;
    const float miL = mi * LOG2E;
    const float* e2p = g_e2 + base + jh * 32;
    float wsum = 0.f;

    unsigned long long acc[4][8];
#pragma unroll
    for (int r = 0; r < 4; r++)
#pragma unroll
        for (int p = 0; p < 8; p++) acc[r][p] = 0ULL;

    for (int jt = 0; jt < 2048; jt += 64) {
        __syncthreads();
        // cooperative h tile load: 64x128 floats = 2048 float4, 16/thread
        {
            const float4* src = (const float4*)(hb + (size_t)jt * 128);
            float4* dst = (float4*)(&hs[0][0]);
#pragma unroll
            for (int q = 0; q < 16; q++) dst[tid + 128 * q] = src[tid + 128 * q];
        }
        // phase A: this thread computes w for (i=iA, 32 j's of its half)
#pragma unroll 4
        for (int q = 0; q < 32; q++) {
            float e2 = __ldg(e2p + jt + q);
            float sp = fmaf(e2, LOG2E, e1L);                             // log2e*(e1+e2)
            float lr = fmaf(ALPHA_LR, fminf(sp, 0.f), fmaxf(sp, 0.f));  // log2e*LR(s)
            float w  = ex2_approx(lr - miL);                            // arg <= 0
            wsum += w;
            wt[jh * 32 + q][iA] = w;                                    // coalesced STS.32
        }
        __syncthreads();

        // phase B: pure FMA rank-64 update, 32 FFMA2 per j per thread
#pragma unroll 2
        for (int j = 0; j < 64; j++) {
            float4 wv = *(const float4*)(&wt[j][ti * 4]);               // 1 LDS.128
            unsigned long long w0 = pack_dup(wv.x);
            unsigned long long w1 = pack_dup(wv.y);
            unsigned long long w2 = pack_dup(wv.z);
            unsigned long long w3 = pack_dup(wv.w);
            const ulonglong2* hr = (const ulonglong2*)(&hs[j][tf * 16]); // 4 LDS.128
            ulonglong2 h0 = hr[0], h1 = hr[1], h2 = hr[2], h3 = hr[3];
#pragma unroll
            for (int r = 0; r < 4; r++) {
                unsigned long long wr = (r == 0) ? w0 : (r == 1) ? w1 : (r == 2) ? w2 : w3;
                fma2(acc[r][0], h0.x, wr);
                fma2(acc[r][1], h0.y, wr);
                fma2(acc[r][2], h1.x, wr);
                fma2(acc[r][3], h1.y, wr);
                fma2(acc[r][4], h2.x, wr);
                fma2(acc[r][5], h2.y, wr);
                fma2(acc[r][6], h3.x, wr);
                fma2(acc[r][7], h3.y, wr);
            }
        }
    }

    // combine the two per-half wsums (block-private global scratch; __syncthreads
    // orders global accesses within the block)
    if (jh == 0) g_wsum[base + i0 + iA] = wsum;
    __syncthreads();
    if (jh == 1) g_wsum[base + i0 + iA] += wsum;
    __syncthreads();

    // epilogue: normalize, residual, elu, store
#pragma unroll
    for (int r = 0; r < 4; r++) {
        const int i = i0 + ti * 4 + r;
        const float rs = 1.0f / g_wsum[base + i];
        const float* hrow = hb + (size_t)i * 128 + tf * 16;
        float* orow = out + (base + i) * 128 + tf * 16;
#pragma unroll
        for (int p = 0; p < 4; p++) {
            float p0, p1;
            unpack2(acc[r][2 * p],     p0, p1);
            float p2, p3;
            unpack2(acc[r][2 * p + 1], p2, p3);
            float4 hv = *(const float4*)(hrow + p * 4);
            float4 o;
            float x;
            x = fmaf(p0, rs, ALPHA_LR * hv.x); o.x = x > 0.f ? x : expm1f(x);
            x = fmaf(p1, rs, ALPHA_LR * hv.y); o.y = x > 0.f ? x : expm1f(x);
            x = fmaf(p2, rs, ALPHA_LR * hv.z); o.z = x > 0.f ? x : expm1f(x);
            x = fmaf(p3, rs, ALPHA_LR * hv.w); o.w = x > 0.f ? x : expm1f(x);
            *(float4*)(orow + p * 4) = o;
        }
    }
}

// ---------------------------------------------------------------------------
// Launch: text, adj(UNUSED by reference), W, a
// ---------------------------------------------------------------------------
extern "C" void kernel_launch(void* const* d_in, const int* in_sizes, int n_in,
                              void* d_out, int out_size) {
    const float* text = (const float*)d_in[0];
    const float* W = (const float*)d_in[2];
    const float* a = (const float*)d_in[3];
    float* out = (float*)d_out;

    gemm_h_kernel<<<256, 256>>>(text, W);
    e_kernel<<<2048, 256>>>(a);
    max_kernel<<<8, 256>>>();
    dim3 grid(32, 8);
    attn_kernel<<<grid, 128>>>(out);
}